// round 1
// baseline (speedup 1.0000x reference)
#include <cuda_runtime.h>
#include <cuda_bf16.h>

// Problem constants (from reference):
//   N_B=16, N_T=48, P=100*100=10000, nkl=4 modes: [0,1],[1,-1],[1,0],[1,1]
//   params row stride = 2688 floats
// Output concat (float32):
//   kappa (16,1,10000,48) | m (16,2,10000,48) | H (16,2,2,10000,48) | tau (16,1,10000,48)
//   total = 128 * 480000 = 61,440,000 floats

#define NB   16
#define NT   48
#define PNUM 10000
#define SZ   (PNUM * NT)      // 480000
#define ROW  2688

__device__ __forceinline__ float softplus_f(float x) {
    // jax.nn.softplus = logaddexp(x, 0) = max(x,0) + log1p(exp(-|x|))
    return fmaxf(x, 0.0f) + log1pf(expf(-fabsf(x)));
}

__device__ __forceinline__ void st4(float* dst, const float* v) {
    *reinterpret_cast<float4*>(dst) = make_float4(v[0], v[1], v[2], v[3]);
}

__global__ __launch_bounds__(480)
void decode_param_cnn_fourier_kernel(const float* __restrict__ params,
                                     float* __restrict__ out) {
    __shared__ float pp[448];   // params[b, 0..447] covers all used indices (max 395)

    const int b = blockIdx.y;
    if (threadIdx.x < 448) pp[threadIdx.x] = params[(size_t)b * ROW + threadIdx.x];
    __syncthreads();

    // Thread -> (p, t-group). 12 t-groups of 4 t's each. Linear in g, so warp
    // stores are fully contiguous (16B per thread per output region).
    const int g  = blockIdx.x * 480 + threadIdx.x;   // 0 .. 119999
    const int tg = g % 12;
    const int p  = g / 12;                            // 0 .. 9999
    const int gx = p / 100;
    const int gy = p - gx * 100;

    // Basis phases: all are 2*pi*m/100, m in [0,100) after mod reduction.
    const float w = 0.06283185307179586f;             // 2*pi/100
    float c0, s0, c1, s1, c2, s2, c3, s3;
    __sincosf(w * (float)gy, &s0, &c0);               // mode 0: [0,1]
    int m1i = gx - gy; if (m1i < 0) m1i += 100;
    __sincosf(w * (float)m1i, &s1, &c1);              // mode 1: [1,-1]
    __sincosf(w * (float)gx, &s2, &c2);               // mode 2: [1,0]
    int m3i = gx + gy; if (m3i >= 100) m3i -= 100;
    __sincosf(w * (float)m3i, &s3, &c3);              // mode 3: [1,1]

    // t-independent part: modes 1..3 (param starts 8 / 40 / 52) + const offsets (46..51)
    float S[6];
#pragma unroll
    for (int f = 0; f < 6; f++) {
        float acc = pp[46 + f];
        acc = fmaf(pp[ 8 + 2 * f], c1, acc);
        acc = fmaf(pp[ 9 + 2 * f], s1, acc);
        acc = fmaf(pp[40 + 2 * f], c2, acc);
        acc = fmaf(pp[41 + 2 * f], s2, acc);
        acc = fmaf(pp[52 + 2 * f], c3, acc);
        acc = fmaf(pp[53 + 2 * f], s3, acc);
        S[f] = acc;
    }

    const float gamma = softplus_f(pp[44]);
    const float beta  = softplus_f(pp[45]);

    const int t0 = tg * 4;
    float kv[4], m1v[4], m2v[4], h00v[4], h01v[4], h11v[4], tv[4];

#pragma unroll
    for (int j = 0; j < 4; j++) {
        const int s = 8 * (t0 + j) + 8;   // mode-0 coeff start for this t
        const float f0 = fmaf(pp[s + 0],  c0, fmaf(pp[s + 1],  s0, S[0]));
        const float f1 = fmaf(pp[s + 2],  c0, fmaf(pp[s + 3],  s0, S[1]));
        const float f2 = fmaf(pp[s + 4],  c0, fmaf(pp[s + 5],  s0, S[2]));
        const float vx = fmaf(pp[s + 6],  c0, fmaf(pp[s + 7],  s0, S[3]));
        const float vy = fmaf(pp[s + 8],  c0, fmaf(pp[s + 9],  s0, S[4]));
        const float f5 = fmaf(pp[s + 10], c0, fmaf(pp[s + 11], s0, S[5]));

        kv[j]   = softplus_f(f0);
        m1v[j]  = f1;
        m2v[j]  = f2;
        h00v[j] = fmaf(beta * vx, vx, gamma);
        h01v[j] = beta * vx * vy;
        h11v[j] = fmaf(beta * vy, vy, gamma);
        tv[j]   = softplus_f(f5);
    }

    const size_t base = (size_t)p * NT + (size_t)t0;   // aligned to 4 floats

    st4(out + (size_t)b * SZ                  + base, kv);    // kappa[b,0,p,t]
    st4(out + (size_t)(16 + 2 * b + 0) * SZ   + base, m1v);   // m[b,0,p,t]
    st4(out + (size_t)(16 + 2 * b + 1) * SZ   + base, m2v);   // m[b,1,p,t]
    st4(out + (size_t)(48 + 4 * b + 0) * SZ   + base, h00v);  // H[b,0,0,p,t]
    st4(out + (size_t)(48 + 4 * b + 1) * SZ   + base, h01v);  // H[b,0,1,p,t]
    st4(out + (size_t)(48 + 4 * b + 2) * SZ   + base, h01v);  // H[b,1,0,p,t]
    st4(out + (size_t)(48 + 4 * b + 3) * SZ   + base, h11v);  // H[b,1,1,p,t]
    st4(out + (size_t)(112 + b) * SZ          + base, tv);    // tau[b,0,p,t]
}

extern "C" void kernel_launch(void* const* d_in, const int* in_sizes, int n_in,
                              void* d_out, int out_size) {
    const float* params = (const float*)d_in[0];
    float* out = (float*)d_out;
    // 16 b-slices (grid.y), each with 10000 p * 12 t-groups = 120000 threads
    dim3 grid(250, NB, 1);
    dim3 block(480, 1, 1);
    decode_param_cnn_fourier_kernel<<<grid, block>>>(params, out);
}

// round 5
// speedup vs baseline: 1.8650x; 1.8650x over previous
#include <cuda_runtime.h>
#include <cuda_bf16.h>

// Problem constants (from reference):
//   N_B=16, N_T=48, P=100*100=10000, nkl=4 modes: [0,1],[1,-1],[1,0],[1,1]
//   params row stride = 2688 floats
// Output concat (float32):
//   kappa (16,1,10000,48) | m (16,2,10000,48) | H (16,2,2,10000,48) | tau (16,1,10000,48)
//   total = 128 * 480000 = 61,440,000 floats = 245.76 MB of pure writes.

#define NB   16
#define NT   48
#define PNUM 10000
#define SZ   (PNUM * NT)      // 480000
#define ROW  2688

// Shared-memory bank-conflict padding: +1 float per 32, applied PER ELEMENT.
// Hot reads: base s = 8t+8 with t = 4*tg + j. Across a warp at fixed (j,c),
// the 12 tg values give logical addresses with stride 32 floats -> same bank
// without padding (12-way conflict). With pad(i)=i+(i>>5) each (j,c) maps to
// 33*tg + const -> 12 distinct banks. PAD must be applied to the full index
// s+c (s mod 32 can be 24, where offsets 8..11 cross a pad block).
#define PAD(i) ((i) + ((i) >> 5))

__device__ __forceinline__ float softplus_f(float x) {
    // jax.nn.softplus = max(x,0) + log1p(exp(-|x|))
    return fmaxf(x, 0.0f) + log1pf(expf(-fabsf(x)));
}

__device__ __forceinline__ void st4cs(float* dst, const float* v) {
    // Streaming store intrinsic: output is write-once, never re-read here.
    __stcs(reinterpret_cast<float4*>(dst), make_float4(v[0], v[1], v[2], v[3]));
}

__global__ __launch_bounds__(480)
void decode_param_cnn_fourier_kernel(const float* __restrict__ params,
                                     float* __restrict__ out) {
    __shared__ float pp[PAD(447) + 1];   // padded; logical indices 0..447

    const int b = blockIdx.y;
    if (threadIdx.x < 448) pp[PAD(threadIdx.x)] = params[(size_t)b * ROW + threadIdx.x];
    __syncthreads();

    // Thread -> (p, t-group of 4). Linear in g so each warp's stores are
    // fully contiguous 512B runs in every output region.
    const int g  = blockIdx.x * 480 + threadIdx.x;   // 0 .. 119999
    const int tg = g % 12;
    const int p  = g / 12;                            // 0 .. 9999
    const int gx = p / 100;
    const int gy = p - gx * 100;

    // All phases are 2*pi*m/100 with integer m reduced into [0,100).
    const float w = 0.06283185307179586f;             // 2*pi/100
    float c0, s0, c1, s1, c2, s2, c3, s3;
    __sincosf(w * (float)gy, &s0, &c0);               // mode 0: [0,1]
    int m1i = gx - gy; if (m1i < 0) m1i += 100;
    __sincosf(w * (float)m1i, &s1, &c1);              // mode 1: [1,-1]
    __sincosf(w * (float)gx, &s2, &c2);               // mode 2: [1,0]
    int m3i = gx + gy; if (m3i >= 100) m3i -= 100;
    __sincosf(w * (float)m3i, &s3, &c3);              // mode 3: [1,1]

    // t-independent part: modes 1..3 (starts 8 / 40 / 52) + const offsets (46..51).
    // These reads are uniform across the block -> smem broadcast, conflict-free.
    float S[6];
#pragma unroll
    for (int f = 0; f < 6; f++) {
        float acc = pp[PAD(46 + f)];
        acc = fmaf(pp[PAD( 8 + 2 * f)], c1, acc);
        acc = fmaf(pp[PAD( 9 + 2 * f)], s1, acc);
        acc = fmaf(pp[PAD(40 + 2 * f)], c2, acc);
        acc = fmaf(pp[PAD(41 + 2 * f)], s2, acc);
        acc = fmaf(pp[PAD(52 + 2 * f)], c3, acc);
        acc = fmaf(pp[PAD(53 + 2 * f)], s3, acc);
        S[f] = acc;
    }

    const float gamma = softplus_f(pp[PAD(44)]);
    const float beta  = softplus_f(pp[PAD(45)]);

    const int t0 = tg * 4;
    float kv[4], m1v[4], m2v[4], h00v[4], h01v[4], h11v[4], tv[4];

#pragma unroll
    for (int j = 0; j < 4; j++) {
        const int s = 8 * (t0 + j) + 8;   // mode-0 coeff start for this t
        // Per-element padded indices: s mod 32 may be 24, where offsets 8..11
        // cross a pad block, so PAD must be applied to each full index.
        const float f0 = fmaf(pp[PAD(s + 0)],  c0, fmaf(pp[PAD(s + 1)],  s0, S[0]));
        const float f1 = fmaf(pp[PAD(s + 2)],  c0, fmaf(pp[PAD(s + 3)],  s0, S[1]));
        const float f2 = fmaf(pp[PAD(s + 4)],  c0, fmaf(pp[PAD(s + 5)],  s0, S[2]));
        const float vx = fmaf(pp[PAD(s + 6)],  c0, fmaf(pp[PAD(s + 7)],  s0, S[3]));
        const float vy = fmaf(pp[PAD(s + 8)],  c0, fmaf(pp[PAD(s + 9)],  s0, S[4]));
        const float f5 = fmaf(pp[PAD(s + 10)], c0, fmaf(pp[PAD(s + 11)], s0, S[5]));

        kv[j]   = softplus_f(f0);
        m1v[j]  = f1;
        m2v[j]  = f2;
        h00v[j] = fmaf(beta * vx, vx, gamma);
        h01v[j] = beta * vx * vy;
        h11v[j] = fmaf(beta * vy, vy, gamma);
        tv[j]   = softplus_f(f5);
    }

    const size_t base = (size_t)p * NT + (size_t)t0;   // 16B-aligned

    st4cs(out + (size_t)b * SZ                + base, kv);    // kappa[b,0,p,t]
    st4cs(out + (size_t)(16 + 2 * b + 0) * SZ + base, m1v);   // m[b,0,p,t]
    st4cs(out + (size_t)(16 + 2 * b + 1) * SZ + base, m2v);   // m[b,1,p,t]
    st4cs(out + (size_t)(48 + 4 * b + 0) * SZ + base, h00v);  // H[b,0,0,p,t]
    st4cs(out + (size_t)(48 + 4 * b + 1) * SZ + base, h01v);  // H[b,0,1,p,t]
    st4cs(out + (size_t)(48 + 4 * b + 2) * SZ + base, h01v);  // H[b,1,0,p,t]
    st4cs(out + (size_t)(48 + 4 * b + 3) * SZ + base, h11v);  // H[b,1,1,p,t]
    st4cs(out + (size_t)(112 + b) * SZ        + base, tv);    // tau[b,0,p,t]
}

extern "C" void kernel_launch(void* const* d_in, const int* in_sizes, int n_in,
                              void* d_out, int out_size) {
    const float* params = (const float*)d_in[0];
    float* out = (float*)d_out;
    dim3 grid(250, NB, 1);
    dim3 block(480, 1, 1);
    decode_param_cnn_fourier_kernel<<<grid, block>>>(params, out);
}

// round 6
// speedup vs baseline: 2.1438x; 1.1495x over previous
#include <cuda_runtime.h>
#include <cuda_bf16.h>

// Problem constants:
//   N_B=16, N_T=48, P=10000, modes [0,1],[1,-1],[1,0],[1,1]; params row = 2688 floats.
// Output concat (float32):
//   kappa (16,1,10000,48) | m (16,2,10000,48) | H (16,2,2,10000,48) | tau (16,1,10000,48)
//   = 245.76 MB pure writes -> DRAM-write floor ~38us at ~6.5TB/s achievable.

#define NB   16
#define NT   48
#define SZ   480000           // 10000 * 48
#define ROW  2688

// Padded smem layout: logical i lives at i + (i>>5)  (stride-33 per 32-block).
#define PAD(i) ((i) + ((i) >> 5))
// Hot-loop offsets: logical index = 32*tg + r, r = 8j+8+c in [8,43].
// Physical = 33*tg + r + (r>>5): base 33*tg at runtime, OFF(j,c) compile-time.
#define OFF(j,c) ((8*(j)+8+(c)) + ((8*(j)+8+(c)) >> 5))

__device__ __forceinline__ float softplus_fast(float x) {
    // max(x,0) + log(1+exp(-|x|)) via MUFU (EX2/LG2). rel err ~2^-21 << 1e-3 budget.
    float e = __expf(-fabsf(x));
    return fmaxf(x, 0.0f) + __logf(1.0f + e);
}

__device__ __forceinline__ void st4cs(float* dst, float a, float b, float c, float d) {
    __stcs(reinterpret_cast<float4*>(dst), make_float4(a, b, c, d));
}

__global__ __launch_bounds__(480)
void decode_param_cnn_fourier_kernel(const float* __restrict__ params,
                                     float* __restrict__ out) {
    __shared__ float pp[PAD(447) + 1];   // padded params row
    __shared__ float Ssh[40 * 8];        // per-p: S0..S5, c0, s0
    __shared__ float gb[2];              // gamma, beta

    const int tid = threadIdx.x;
    const int b   = blockIdx.y;
    if (tid < 448) pp[PAD(tid)] = params[(size_t)b * ROW + tid];
    __syncthreads();

    const float w = 0.06283185307179586f;   // 2*pi/100

    // Per-(b,p) precompute: block covers p in [40*blockIdx.x, +40).
    // 240 threads: (pl, f) each compute one S entry; f==0 also writes mode-0 trig.
    if (tid < 240) {
        const int pl = tid / 6, f = tid - pl * 6;
        const int p2 = blockIdx.x * 40 + pl;
        const int gx = p2 / 100, gy = p2 - gx * 100;
        int m1 = gx - gy; if (m1 < 0)   m1 += 100;
        int m3 = gx + gy; if (m3 >= 100) m3 -= 100;
        float c1, s1, c2, s2, c3, s3;
        __sincosf(w * (float)m1, &s1, &c1);   // mode [1,-1]
        __sincosf(w * (float)gx, &s2, &c2);   // mode [1,0]
        __sincosf(w * (float)m3, &s3, &c3);   // mode [1,1]
        float acc = pp[PAD(46 + f)];          // constant offset term
        acc = fmaf(pp[PAD( 8 + 2 * f)], c1, acc);
        acc = fmaf(pp[PAD( 9 + 2 * f)], s1, acc);
        acc = fmaf(pp[PAD(40 + 2 * f)], c2, acc);
        acc = fmaf(pp[PAD(41 + 2 * f)], s2, acc);
        acc = fmaf(pp[PAD(52 + 2 * f)], c3, acc);
        acc = fmaf(pp[PAD(53 + 2 * f)], s3, acc);
        Ssh[pl * 8 + f] = acc;
        if (f == 0) {
            float c0, s0;
            __sincosf(w * (float)gy, &s0, &c0);   // mode [0,1]
            Ssh[pl * 8 + 6] = c0;
            Ssh[pl * 8 + 7] = s0;
        }
    }
    if (tid == 240) {
        gb[0] = softplus_fast(pp[PAD(44)]);
        gb[1] = softplus_fast(pp[PAD(45)]);
    }
    __syncthreads();

    // Main: thread = (p-local, t-group of 4). Linear tid -> contiguous warp stores.
    const int tg = tid % 12;
    const int pl = tid / 12;
    const int p  = blockIdx.x * 40 + pl;

    // Padded base for this thread's coeff window; all loads use immediate offsets.
    const float* __restrict__ q = pp + 33 * tg;

    const float S0 = Ssh[pl * 8 + 0], S1 = Ssh[pl * 8 + 1], S2 = Ssh[pl * 8 + 2];
    const float S3 = Ssh[pl * 8 + 3], S4 = Ssh[pl * 8 + 4], S5 = Ssh[pl * 8 + 5];
    const float c0 = Ssh[pl * 8 + 6], s0 = Ssh[pl * 8 + 7];
    const float gamma = gb[0], beta = gb[1];

    float kv[4], m1v[4], m2v[4], h00v[4], h01v[4], h11v[4], tv[4];

#pragma unroll
    for (int j = 0; j < 4; j++) {
        const float f0 = fmaf(q[OFF(j, 0)],  c0, fmaf(q[OFF(j, 1)],  s0, S0));
        const float f1 = fmaf(q[OFF(j, 2)],  c0, fmaf(q[OFF(j, 3)],  s0, S1));
        const float f2 = fmaf(q[OFF(j, 4)],  c0, fmaf(q[OFF(j, 5)],  s0, S2));
        const float vx = fmaf(q[OFF(j, 6)],  c0, fmaf(q[OFF(j, 7)],  s0, S3));
        const float vy = fmaf(q[OFF(j, 8)],  c0, fmaf(q[OFF(j, 9)],  s0, S4));
        const float f5 = fmaf(q[OFF(j, 10)], c0, fmaf(q[OFF(j, 11)], s0, S5));

        kv[j]  = softplus_fast(f0);
        m1v[j] = f1;
        m2v[j] = f2;
        const float bvx = beta * vx;
        h00v[j] = fmaf(bvx, vx, gamma);
        h01v[j] = bvx * vy;
        h11v[j] = fmaf(beta * vy, vy, gamma);
        tv[j]  = softplus_fast(f5);
    }

    const size_t base = (size_t)p * NT + (size_t)(tg * 4);   // 16B-aligned

    st4cs(out + (size_t)b * SZ                + base, kv[0],  kv[1],  kv[2],  kv[3]);
    st4cs(out + (size_t)(16 + 2 * b + 0) * SZ + base, m1v[0], m1v[1], m1v[2], m1v[3]);
    st4cs(out + (size_t)(16 + 2 * b + 1) * SZ + base, m2v[0], m2v[1], m2v[2], m2v[3]);
    st4cs(out + (size_t)(48 + 4 * b + 0) * SZ + base, h00v[0], h00v[1], h00v[2], h00v[3]);
    st4cs(out + (size_t)(48 + 4 * b + 1) * SZ + base, h01v[0], h01v[1], h01v[2], h01v[3]);
    st4cs(out + (size_t)(48 + 4 * b + 2) * SZ + base, h01v[0], h01v[1], h01v[2], h01v[3]);
    st4cs(out + (size_t)(48 + 4 * b + 3) * SZ + base, h11v[0], h11v[1], h11v[2], h11v[3]);
    st4cs(out + (size_t)(112 + b) * SZ        + base, tv[0],  tv[1],  tv[2],  tv[3]);
}

extern "C" void kernel_launch(void* const* d_in, const int* in_sizes, int n_in,
                              void* d_out, int out_size) {
    const float* params = (const float*)d_in[0];
    float* out = (float*)d_out;
    dim3 grid(250, NB, 1);    // 250 blocks * 40 p each; y = batch
    dim3 block(480, 1, 1);
    decode_param_cnn_fourier_kernel<<<grid, block>>>(params, out);
}